// round 14
// baseline (speedup 1.0000x reference)
#include <cuda_runtime.h>
#include <math.h>
#include <stdint.h>

#define NOBJ  2048
#define EMBED 256
#define NHD   8
#define NP    32
#define HD    32
#define FFN_D 1024
#define HIMG  160
#define WIMG  160
#define HW    (HIMG*WIMG)

// ---- scratch (device globals; no allocations allowed) ----
__device__ float g_loc  [NOBJ*NHD*NP*2];
__device__ float g_attn [NOBJ*EMBED];
__device__ float g_x1ln [NOBJ*EMBED];
__device__ float g_hid  [NOBJ*FFN_D];
__device__ float g_part [2*NOBJ*512];     // split-K partials (max 2x1M / 4x512K)

// ============================================================================
// f32x2 helpers (packed dual-lane fp32 FMA)
// ============================================================================
__device__ __forceinline__ unsigned long long pack2(float x) {
    unsigned long long r;
    asm("mov.b64 %0, {%1, %1};" : "=l"(r) : "r"(__float_as_uint(x)));
    return r;
}
__device__ __forceinline__ void ffma2(unsigned long long& d,
                                      unsigned long long a, unsigned long long b) {
    asm("fma.rn.f32x2 %0, %1, %2, %0;" : "+l"(d) : "l"(a), "l"(b));
}
__device__ __forceinline__ float2 unpack2(unsigned long long v) {
    unsigned lo, hi;
    asm("mov.b64 {%0, %1}, %2;" : "=r"(lo), "=r"(hi) : "l"(v));
    return make_float2(__uint_as_float(lo), __uint_as_float(hi));
}

// ============================================================================
// FFMA2 GEMM: C = A(M x kLen slice) @ B(KxN), row-major.
// Tile 128x64, 256 thr (8 warps), per-thread 4m x 8n. k-chunk 16,
// double-buffered smem, ONE sync per chunk, 2 CTAs/SM.
// blockIdx.z = K slice. EPI 2: relu(+bias)   EPI 4: raw partial
// ============================================================================
template<int EPI>
__global__ __launch_bounds__(256, 2) void fgemm(
    const float* __restrict__ A, const float* __restrict__ B,
    const float* __restrict__ bias, float* __restrict__ C,
    int M, int N, int K, int kLen)
{
    __shared__ __align__(16) float As[2][16][132];   // [buf][k][m]
    __shared__ __align__(16) float Bs[2][16][68];    // [buf][k][n]

    const int tid  = threadIdx.x;
    const int tx   = tid & 7;
    const int ty   = tid >> 3;
    const int row0 = blockIdx.y * 128;
    const int col0 = blockIdx.x * 64;
    const int kBase = blockIdx.z * kLen;

    unsigned long long acc[4][4];
#pragma unroll
    for (int i = 0; i < 4; i++)
#pragma unroll
        for (int j = 0; j < 4; j++) acc[i][j] = 0ull;

    const int am0 = tid >> 2;
    const int ak  = (tid & 3) << 2;
    const int bk  = tid >> 4;
    const int bn  = (tid & 15) << 2;

    const int S = kLen >> 4;

    float4 aR0 = *(const float4*)(A + (size_t)(row0 + am0)      * K + kBase + ak);
    float4 aR1 = *(const float4*)(A + (size_t)(row0 + am0 + 64) * K + kBase + ak);
    float4 bR  = *(const float4*)(B + (size_t)(kBase + bk) * N + col0 + bn);

    for (int c = 0; c < S; c++) {
        const int b = c & 1;
        As[b][ak + 0][am0]      = aR0.x;
        As[b][ak + 1][am0]      = aR0.y;
        As[b][ak + 2][am0]      = aR0.z;
        As[b][ak + 3][am0]      = aR0.w;
        As[b][ak + 0][am0 + 64] = aR1.x;
        As[b][ak + 1][am0 + 64] = aR1.y;
        As[b][ak + 2][am0 + 64] = aR1.z;
        As[b][ak + 3][am0 + 64] = aR1.w;
        *(float4*)&Bs[b][bk][bn] = bR;
        __syncthreads();

        if (c + 1 < S) {
            int k0 = kBase + (c + 1) * 16;
            aR0 = *(const float4*)(A + (size_t)(row0 + am0)      * K + k0 + ak);
            aR1 = *(const float4*)(A + (size_t)(row0 + am0 + 64) * K + k0 + ak);
            bR  = *(const float4*)(B + (size_t)(k0 + bk) * N + col0 + bn);
        }

#pragma unroll
        for (int k = 0; k < 16; k++) {
            float4 a4 = *(const float4*)&As[b][k][ty * 4];
            unsigned long long ap0 = pack2(a4.x);
            unsigned long long ap1 = pack2(a4.y);
            unsigned long long ap2 = pack2(a4.z);
            unsigned long long ap3 = pack2(a4.w);
            float4 bq0 = *(const float4*)&Bs[b][k][tx * 8];
            float4 bq1 = *(const float4*)&Bs[b][k][tx * 8 + 4];
            unsigned long long b0, b1, b2, b3;
            asm("mov.b64 %0, {%1, %2};" : "=l"(b0) : "r"(__float_as_uint(bq0.x)), "r"(__float_as_uint(bq0.y)));
            asm("mov.b64 %0, {%1, %2};" : "=l"(b1) : "r"(__float_as_uint(bq0.z)), "r"(__float_as_uint(bq0.w)));
            asm("mov.b64 %0, {%1, %2};" : "=l"(b2) : "r"(__float_as_uint(bq1.x)), "r"(__float_as_uint(bq1.y)));
            asm("mov.b64 %0, {%1, %2};" : "=l"(b3) : "r"(__float_as_uint(bq1.z)), "r"(__float_as_uint(bq1.w)));
            ffma2(acc[0][0], ap0, b0); ffma2(acc[0][1], ap0, b1);
            ffma2(acc[0][2], ap0, b2); ffma2(acc[0][3], ap0, b3);
            ffma2(acc[1][0], ap1, b0); ffma2(acc[1][1], ap1, b1);
            ffma2(acc[1][2], ap1, b2); ffma2(acc[1][3], ap1, b3);
            ffma2(acc[2][0], ap2, b0); ffma2(acc[2][1], ap2, b1);
            ffma2(acc[2][2], ap2, b2); ffma2(acc[2][3], ap2, b3);
            ffma2(acc[3][0], ap3, b0); ffma2(acc[3][1], ap3, b1);
            ffma2(acc[3][2], ap3, b2); ffma2(acc[3][3], ap3, b3);
        }
    }

#pragma unroll
    for (int mi = 0; mi < 4; mi++) {
        const int r = row0 + ty * 4 + mi;
#pragma unroll
        for (int nj = 0; nj < 4; nj++) {
            const int cidx = col0 + tx * 8 + 2 * nj;
            float2 v = unpack2(acc[mi][nj]);
            size_t oidx = (size_t)r * N + cidx;
            float2 o;
            if (EPI == 2) {
                o.x = fmaxf(v.x + bias[cidx],     0.f);
                o.y = fmaxf(v.y + bias[cidx + 1], 0.f);
            } else {                               // EPI 4: raw partial
                o.x = v.x; o.y = v.y;
                oidx += (size_t)blockIdx.z * M * N;
            }
            *(float2*)(C + oidx) = o;
        }
    }
}

// ============================================================================
// Combine 2 offset-GEMM partials + bias -> sample coords. 1 thread = 1 (x,y).
// ============================================================================
__global__ __launch_bounds__(256) void coords_k(
    const float* __restrict__ part, const float* __restrict__ bias,
    const float* __restrict__ xy,   const float* __restrict__ strd,
    float* __restrict__ C)
{
    const int i   = blockIdx.x * 256 + threadIdx.x;   // 0 .. NOBJ*256-1
    const int row = i >> 8;
    const int col = (i & 255) * 2;
    const size_t idx = (size_t)row * 512 + col;
    const size_t half = (size_t)NOBJ * 512;
    float v0 = part[idx]     + part[half + idx]     + bias[col];
    float v1 = part[idx + 1] + part[half + idx + 1] + bias[col + 1];
    float st = strd[row], bx = xy[2 * row], by = xy[2 * row + 1];
    float lx = bx + v0 * st;
    float ly = by + v1 * st;
    float gx = lx * (2.0f / 640.0f) - 1.0f;
    float gy = ly * (2.0f / 640.0f) - 1.0f;
    float2 o;
    o.x = ((gx + 1.0f) * 160.0f - 1.0f) * 0.5f;
    o.y = ((gy + 1.0f) * 160.0f - 1.0f) * 0.5f;
    *(float2*)(C + idx) = o;
}

// ============================================================================
// Combine NPART split-K partials + bias + residual, then LayerNorm.
// ============================================================================
template<int NPART>
__global__ __launch_bounds__(256) void comb_ln_k(
    const float* __restrict__ part, const float* __restrict__ bias,
    const float* __restrict__ res,  const float* __restrict__ g,
    const float* __restrict__ b,    float* __restrict__ y)
{
    __shared__ float red[8];
    const int r = blockIdx.x, t = threadIdx.x;
    const size_t idx = (size_t)r * EMBED + t;
    float v = bias[t] + res[idx];
#pragma unroll
    for (int i = 0; i < NPART; i++)
        v += part[(size_t)i * NOBJ * EMBED + idx];

    float s = v;
#pragma unroll
    for (int o = 16; o; o >>= 1) s += __shfl_xor_sync(0xffffffffu, s, o);
    if ((t & 31) == 0) red[t >> 5] = s;
    __syncthreads();
    float tot = 0.f;
#pragma unroll
    for (int i = 0; i < 8; i++) tot += red[i];
    float mean = tot * (1.f / 256.f);
    float d = v - mean;
    __syncthreads();

    s = d * d;
#pragma unroll
    for (int o = 16; o; o >>= 1) s += __shfl_xor_sync(0xffffffffu, s, o);
    if ((t & 31) == 0) red[t >> 5] = s;
    __syncthreads();
    tot = 0.f;
#pragma unroll
    for (int i = 0; i < 8; i++) tot += red[i];
    float inv = rsqrtf(tot * (1.f / 256.f) + 1e-5f);
    y[idx] = d * inv * g[t] + b[t];
}

// ============================================================================
// Sampler (planar, known-good): 1 block/object, warp = head, lane = point
// ============================================================================
__global__ __launch_bounds__(256) void sampler_k(
    const float* __restrict__ query, const float* __restrict__ key,
    const float* __restrict__ val,   const float* __restrict__ x2d,
    const float* __restrict__ maskp, const int*   __restrict__ imgind,
    const float* __restrict__ loc,
    float* __restrict__ outv, float* __restrict__ outa,
    float* __restrict__ outm, float* __restrict__ outx,
    float* __restrict__ attn)
{
    __shared__ float qs  [NHD][HD];
    __shared__ float vsm [NHD][HD][NP + 1];
    __shared__ float asms[NHD][NP];

    const int n   = blockIdx.x;
    const int tid = threadIdx.x;
    const int h   = tid >> 5;
    const int p   = tid & 31;

    qs[h][p] = query[(size_t)n * EMBED + h * HD + p];
    const int img = imgind[n];

    float2 l2 = ((const float2*)loc)[((size_t)n * NHD + h) * NP + p];
    float ix = l2.x, iy = l2.y;
    float x0f = floorf(ix), y0f = floorf(iy);
    float wx1 = ix - x0f,   wy1 = iy - y0f;
    float wx0 = 1.f - wx1,  wy0 = 1.f - wy1;
    int x0 = (int)x0f, y0 = (int)y0f;
    int x1i = x0 + 1,  y1i = y0 + 1;
    int xc0 = min(max(x0, 0), WIMG - 1), xc1 = min(max(x1i, 0), WIMG - 1);
    int yc0 = min(max(y0, 0), HIMG - 1), yc1 = min(max(y1i, 0), HIMG - 1);
    float w00 = wx0 * wy0, w10 = wx1 * wy0, w01 = wx0 * wy1, w11 = wx1 * wy1;
    int o00 = yc0 * WIMG + xc0, o10 = yc0 * WIMG + xc1;
    int o01 = yc1 * WIMG + xc0, o11 = yc1 * WIMG + xc1;

    const float* kb = key + ((size_t)img * EMBED + h * HD) * HW;
    const float* vb = val + ((size_t)img * EMBED + h * HD) * HW;

    __syncwarp();

    float a = 0.f;
    float* outvb = outv + (((size_t)n * NHD + h) * HD) * NP + p;
#pragma unroll 4
    for (int d = 0; d < HD; d++) {
        const float* kp = kb + d * HW;
        float ks = w00 * kp[o00] + w10 * kp[o10] + w01 * kp[o01] + w11 * kp[o11];
        a += qs[h][d] * ks;
        const float* vp = vb + d * HW;
        float vs = w00 * vp[o00] + w10 * vp[o10] + w01 * vp[o01] + w11 * vp[o11];
        vsm[h][d][p] = vs;
        outvb[d * NP] = vs;
    }
    a *= 0.17677669529663687f;
    size_t baseNP = ((size_t)n * NHD + h) * NP + p;
    outa[baseNP] = a;

    bool vx0 = (x0  >= 0) && (x0  < WIMG), vx1 = (x1i >= 0) && (x1i < WIMG);
    bool vy0 = (y0  >= 0) && (y0  < HIMG), vy1 = (y1i >= 0) && (y1i < HIMG);
    const float* mb = maskp + (size_t)img * HW;
    float mval = 0.f;
    if (vx0 && vy0) mval += w00 * mb[o00];
    if (vx1 && vy0) mval += w10 * mb[o10];
    if (vx0 && vy1) mval += w01 * mb[o01];
    if (vx1 && vy1) mval += w11 * mb[o11];
    outm[baseNP] = mval;

    const float* xb0 = x2d + (size_t)img * 2 * HW;
    const float* xb1 = xb0 + HW;
    float xs0 = w00 * xb0[o00] + w10 * xb0[o10] + w01 * xb0[o01] + w11 * xb0[o11];
    float xs1 = w00 * xb1[o00] + w10 * xb1[o10] + w01 * xb1[o01] + w11 * xb1[o11];
    size_t xbase = (((size_t)n * NHD + h) * 2) * NP + p;
    outx[xbase]      = xs0;
    outx[xbase + NP] = xs1;

    float mx = a;
#pragma unroll
    for (int o = 16; o; o >>= 1) mx = fmaxf(mx, __shfl_xor_sync(0xffffffffu, mx, o));
    float e = expf(a - mx);
    float ssum = e;
#pragma unroll
    for (int o = 16; o; o >>= 1) ssum += __shfl_xor_sync(0xffffffffu, ssum, o);
    float asv = e / ssum * mval;
    asms[h][p] = asv;
    __syncwarp();

    const int d = p;
    float o = 0.f;
#pragma unroll
    for (int pp = 0; pp < NP; pp++) o += asms[h][pp] * vsm[h][d][pp];
    attn[(size_t)n * EMBED + h * HD + d] = o;
}

// ============================================================================
extern "C" void kernel_launch(void* const* d_in, const int* in_sizes, int n_in,
                              void* d_out, int out_size)
{
    const float* query   = (const float*)d_in[0];
    const float* obj_emb = (const float*)d_in[1];
    const float* key_f   = (const float*)d_in[2];
    const float* value   = (const float*)d_in[3];
    const float* x2d     = (const float*)d_in[4];
    const float* maskp   = (const float*)d_in[5];
    const float* xy      = (const float*)d_in[6];
    const float* strides = (const float*)d_in[7];
    const int*   imgind  = (const int*  )d_in[8];
    const float* w_off   = (const float*)d_in[9];
    const float* b_off   = (const float*)d_in[10];
    const float* w_out   = (const float*)d_in[11];
    const float* b_out   = (const float*)d_in[12];
    const float* ln1g    = (const float*)d_in[13];
    const float* ln1b    = (const float*)d_in[14];
    const float* w1      = (const float*)d_in[15];
    const float* b1      = (const float*)d_in[16];
    const float* w2      = (const float*)d_in[17];
    const float* b2      = (const float*)d_in[18];
    const float* ln2g    = (const float*)d_in[19];
    const float* ln2b    = (const float*)d_in[20];

    float* out  = (float*)d_out;
    float* outv = out  + (size_t)NOBJ * EMBED;
    float* outa = outv + (size_t)NOBJ * NHD * HD * NP;
    float* outm = outa + (size_t)NOBJ * NHD * NP;
    float* outx = outm + (size_t)NOBJ * NHD * NP;

    float *p_loc, *p_attn, *p_x1ln, *p_hid, *p_part;
    cudaGetSymbolAddress((void**)&p_loc,  g_loc);
    cudaGetSymbolAddress((void**)&p_attn, g_attn);
    cudaGetSymbolAddress((void**)&p_x1ln, g_x1ln);
    cudaGetSymbolAddress((void**)&p_hid,  g_hid);
    cudaGetSymbolAddress((void**)&p_part, g_part);

    // 1) offsets GEMM (M=2048,N=512,K=256), split-K=2 -> partials (256 blocks)
    fgemm<4><<<dim3(512 / 64, NOBJ / 128, 2), 256>>>(
        obj_emb, w_off, nullptr, p_part, NOBJ, 512, EMBED, EMBED / 2);

    // 2) combine partials + bias -> sample coords
    coords_k<<<NOBJ, 256>>>(p_part, b_off, xy, strides, p_loc);

    // 3) gather + attention + sample outputs
    sampler_k<<<NOBJ, 256>>>(query, key_f, value, x2d, maskp, imgind, p_loc,
                             outv, outa, outm, outx, p_attn);

    // 4) w_out GEMM (K=256), split-K=4 -> partials (256 blocks)
    fgemm<4><<<dim3(EMBED / 64, NOBJ / 128, 4), 256>>>(
        p_attn, w_out, nullptr, p_part, NOBJ, EMBED, EMBED, EMBED / 4);

    // 5) combine + bias + residual(obj_emb) + LN1 -> x1ln
    comb_ln_k<4><<<NOBJ, 256>>>(p_part, b_out, obj_emb, ln1g, ln1b, p_x1ln);

    // 6) FFN up + relu (M=2048,N=1024,K=256) (256 blocks)
    fgemm<2><<<dim3(FFN_D / 64, NOBJ / 128, 1), 256>>>(
        p_x1ln, w1, b1, p_hid, NOBJ, FFN_D, EMBED, EMBED);

    // 7) FFN down GEMM (K=1024), split-K=4 -> partials (256 blocks)
    fgemm<4><<<dim3(EMBED / 64, NOBJ / 128, 4), 256>>>(
        p_hid, w2, nullptr, p_part, NOBJ, EMBED, FFN_D, FFN_D / 4);

    // 8) combine + bias + residual(x1ln) + LN2 -> final out
    comb_ln_k<4><<<NOBJ, 256>>>(p_part, b2, p_x1ln, ln2g, ln2b, out);
}

// round 15
// speedup vs baseline: 1.3255x; 1.3255x over previous
#include <cuda_runtime.h>
#include <math.h>
#include <stdint.h>

#define NOBJ  2048
#define EMBED 256
#define NHD   8
#define NP    32
#define HD    32
#define FFN_D 1024
#define HIMG  160
#define WIMG  160
#define HW    (HIMG*WIMG)

// ---- scratch (device globals; no allocations allowed) ----
__device__ float g_loc  [NOBJ*NHD*NP*2];
__device__ float g_attn [NOBJ*EMBED];
__device__ float g_x1ln [NOBJ*EMBED];
__device__ float g_hid  [NOBJ*FFN_D];
__device__ float g_part [2*NOBJ*512];     // split-K partials

// ============================================================================
// f32x2 helpers
// ============================================================================
__device__ __forceinline__ unsigned long long pack2(float x) {
    unsigned long long r;
    asm("mov.b64 %0, {%1, %1};" : "=l"(r) : "r"(__float_as_uint(x)));
    return r;
}
__device__ __forceinline__ unsigned long long packab(float a, float b) {
    unsigned long long r;
    asm("mov.b64 %0, {%1, %2};" : "=l"(r) : "r"(__float_as_uint(a)), "r"(__float_as_uint(b)));
    return r;
}
__device__ __forceinline__ void ffma2(unsigned long long& d,
                                      unsigned long long a, unsigned long long b) {
    asm("fma.rn.f32x2 %0, %1, %2, %0;" : "+l"(d) : "l"(a), "l"(b));
}
__device__ __forceinline__ float2 unpack2(unsigned long long v) {
    unsigned lo, hi;
    asm("mov.b64 {%0, %1}, %2;" : "=r"(lo), "=r"(hi) : "l"(v));
    return make_float2(__uint_as_float(lo), __uint_as_float(hi));
}

// ============================================================================
// FFMA2 GEMM: C = A(M x kLen slice) @ B(KxN), row-major.
// Tile 128x64, 256 thr, per-thread 4m x 8n. k-chunk 16, double-buffered smem,
// one sync per chunk, software-pipelined register fragments.
// blockIdx.z = K slice. EPI 2: relu(+bias)   EPI 4: raw partial
// ============================================================================
template<int EPI>
__global__ __launch_bounds__(256) void fgemm(
    const float* __restrict__ A, const float* __restrict__ B,
    const float* __restrict__ bias, float* __restrict__ C,
    int M, int N, int K, int kLen)
{
    __shared__ __align__(16) float As[2][16][132];   // [buf][k][m]
    __shared__ __align__(16) float Bs[2][16][68];    // [buf][k][n]

    const int tid  = threadIdx.x;
    const int tx   = tid & 7;
    const int ty   = tid >> 3;
    const int row0 = blockIdx.y * 128;
    const int col0 = blockIdx.x * 64;
    const int kBase = blockIdx.z * kLen;

    unsigned long long acc[4][4];
#pragma unroll
    for (int i = 0; i < 4; i++)
#pragma unroll
        for (int j = 0; j < 4; j++) acc[i][j] = 0ull;

    const int am0 = tid >> 2;
    const int ak  = (tid & 3) << 2;
    const int bk  = tid >> 4;
    const int bn  = (tid & 15) << 2;

    const int S = kLen >> 4;

    float4 aR0 = *(const float4*)(A + (size_t)(row0 + am0)      * K + kBase + ak);
    float4 aR1 = *(const float4*)(A + (size_t)(row0 + am0 + 64) * K + kBase + ak);
    float4 bR  = *(const float4*)(B + (size_t)(kBase + bk) * N + col0 + bn);

    for (int c = 0; c < S; c++) {
        const int b = c & 1;
        As[b][ak + 0][am0]      = aR0.x;
        As[b][ak + 1][am0]      = aR0.y;
        As[b][ak + 2][am0]      = aR0.z;
        As[b][ak + 3][am0]      = aR0.w;
        As[b][ak + 0][am0 + 64] = aR1.x;
        As[b][ak + 1][am0 + 64] = aR1.y;
        As[b][ak + 2][am0 + 64] = aR1.z;
        As[b][ak + 3][am0 + 64] = aR1.w;
        *(float4*)&Bs[b][bk][bn] = bR;
        __syncthreads();

        if (c + 1 < S) {
            int k0 = kBase + (c + 1) * 16;
            aR0 = *(const float4*)(A + (size_t)(row0 + am0)      * K + k0 + ak);
            aR1 = *(const float4*)(A + (size_t)(row0 + am0 + 64) * K + k0 + ak);
            bR  = *(const float4*)(B + (size_t)(k0 + bk) * N + col0 + bn);
        }

        // software-pipelined fragments: load k+1 while computing k
        unsigned long long apf[2][4], bbf[2][4];
        {
            float4 a4  = *(const float4*)&As[b][0][ty * 4];
            float4 bq0 = *(const float4*)&Bs[b][0][tx * 8];
            float4 bq1 = *(const float4*)&Bs[b][0][tx * 8 + 4];
            apf[0][0] = pack2(a4.x); apf[0][1] = pack2(a4.y);
            apf[0][2] = pack2(a4.z); apf[0][3] = pack2(a4.w);
            bbf[0][0] = packab(bq0.x, bq0.y); bbf[0][1] = packab(bq0.z, bq0.w);
            bbf[0][2] = packab(bq1.x, bq1.y); bbf[0][3] = packab(bq1.z, bq1.w);
        }
#pragma unroll
        for (int k = 0; k < 16; k++) {
            const int cur = k & 1, nxt = cur ^ 1;
            if (k < 15) {
                float4 a4  = *(const float4*)&As[b][k + 1][ty * 4];
                float4 bq0 = *(const float4*)&Bs[b][k + 1][tx * 8];
                float4 bq1 = *(const float4*)&Bs[b][k + 1][tx * 8 + 4];
                apf[nxt][0] = pack2(a4.x); apf[nxt][1] = pack2(a4.y);
                apf[nxt][2] = pack2(a4.z); apf[nxt][3] = pack2(a4.w);
                bbf[nxt][0] = packab(bq0.x, bq0.y); bbf[nxt][1] = packab(bq0.z, bq0.w);
                bbf[nxt][2] = packab(bq1.x, bq1.y); bbf[nxt][3] = packab(bq1.z, bq1.w);
            }
#pragma unroll
            for (int mi = 0; mi < 4; mi++) {
                ffma2(acc[mi][0], apf[cur][mi], bbf[cur][0]);
                ffma2(acc[mi][1], apf[cur][mi], bbf[cur][1]);
                ffma2(acc[mi][2], apf[cur][mi], bbf[cur][2]);
                ffma2(acc[mi][3], apf[cur][mi], bbf[cur][3]);
            }
        }
    }

#pragma unroll
    for (int mi = 0; mi < 4; mi++) {
        const int r = row0 + ty * 4 + mi;
#pragma unroll
        for (int nj = 0; nj < 4; nj++) {
            const int cidx = col0 + tx * 8 + 2 * nj;
            float2 v = unpack2(acc[mi][nj]);
            size_t oidx = (size_t)r * N + cidx;
            float2 o;
            if (EPI == 2) {
                o.x = fmaxf(v.x + bias[cidx],     0.f);
                o.y = fmaxf(v.y + bias[cidx + 1], 0.f);
            } else {                               // EPI 4: raw partial
                o.x = v.x; o.y = v.y;
                oidx += (size_t)blockIdx.z * M * N;
            }
            *(float2*)(C + oidx) = o;
        }
    }
}

// ============================================================================
// Combine 2 offset-GEMM partials + bias -> sample coords. 1 thread = 1 (x,y).
// ============================================================================
__global__ __launch_bounds__(256) void coords_k(
    const float* __restrict__ part, const float* __restrict__ bias,
    const float* __restrict__ xy,   const float* __restrict__ strd,
    float* __restrict__ C)
{
    const int i   = blockIdx.x * 256 + threadIdx.x;
    const int row = i >> 8;
    const int col = (i & 255) * 2;
    const size_t idx = (size_t)row * 512 + col;
    const size_t half = (size_t)NOBJ * 512;
    float v0 = part[idx]     + part[half + idx]     + bias[col];
    float v1 = part[idx + 1] + part[half + idx + 1] + bias[col + 1];
    float st = strd[row], bx = xy[2 * row], by = xy[2 * row + 1];
    float lx = bx + v0 * st;
    float ly = by + v1 * st;
    float gx = lx * (2.0f / 640.0f) - 1.0f;
    float gy = ly * (2.0f / 640.0f) - 1.0f;
    float2 o;
    o.x = ((gx + 1.0f) * 160.0f - 1.0f) * 0.5f;
    o.y = ((gy + 1.0f) * 160.0f - 1.0f) * 0.5f;
    *(float2*)(C + idx) = o;
}

// ============================================================================
// Combine NPART split-K partials + bias + residual, then LayerNorm.
// ============================================================================
template<int NPART>
__global__ __launch_bounds__(256) void comb_ln_k(
    const float* __restrict__ part, const float* __restrict__ bias,
    const float* __restrict__ res,  const float* __restrict__ g,
    const float* __restrict__ b,    float* __restrict__ y)
{
    __shared__ float red[8];
    const int r = blockIdx.x, t = threadIdx.x;
    const size_t idx = (size_t)r * EMBED + t;
    float v = bias[t] + res[idx];
#pragma unroll
    for (int i = 0; i < NPART; i++)
        v += part[(size_t)i * NOBJ * EMBED + idx];

    float s = v;
#pragma unroll
    for (int o = 16; o; o >>= 1) s += __shfl_xor_sync(0xffffffffu, s, o);
    if ((t & 31) == 0) red[t >> 5] = s;
    __syncthreads();
    float tot = 0.f;
#pragma unroll
    for (int i = 0; i < 8; i++) tot += red[i];
    float mean = tot * (1.f / 256.f);
    float d = v - mean;
    __syncthreads();

    s = d * d;
#pragma unroll
    for (int o = 16; o; o >>= 1) s += __shfl_xor_sync(0xffffffffu, s, o);
    if ((t & 31) == 0) red[t >> 5] = s;
    __syncthreads();
    tot = 0.f;
#pragma unroll
    for (int i = 0; i < 8; i++) tot += red[i];
    float inv = rsqrtf(tot * (1.f / 256.f) + 1e-5f);
    y[idx] = d * inv * g[t] + b[t];
}

// ============================================================================
// Sampler (planar, known-good): 1 block/object, warp = head, lane = point
// ============================================================================
__global__ __launch_bounds__(256) void sampler_k(
    const float* __restrict__ query, const float* __restrict__ key,
    const float* __restrict__ val,   const float* __restrict__ x2d,
    const float* __restrict__ maskp, const int*   __restrict__ imgind,
    const float* __restrict__ loc,
    float* __restrict__ outv, float* __restrict__ outa,
    float* __restrict__ outm, float* __restrict__ outx,
    float* __restrict__ attn)
{
    __shared__ float qs  [NHD][HD];
    __shared__ float vsm [NHD][HD][NP + 1];
    __shared__ float asms[NHD][NP];

    const int n   = blockIdx.x;
    const int tid = threadIdx.x;
    const int h   = tid >> 5;
    const int p   = tid & 31;

    qs[h][p] = query[(size_t)n * EMBED + h * HD + p];
    const int img = imgind[n];

    float2 l2 = ((const float2*)loc)[((size_t)n * NHD + h) * NP + p];
    float ix = l2.x, iy = l2.y;
    float x0f = floorf(ix), y0f = floorf(iy);
    float wx1 = ix - x0f,   wy1 = iy - y0f;
    float wx0 = 1.f - wx1,  wy0 = 1.f - wy1;
    int x0 = (int)x0f, y0 = (int)y0f;
    int x1i = x0 + 1,  y1i = y0 + 1;
    int xc0 = min(max(x0, 0), WIMG - 1), xc1 = min(max(x1i, 0), WIMG - 1);
    int yc0 = min(max(y0, 0), HIMG - 1), yc1 = min(max(y1i, 0), HIMG - 1);
    float w00 = wx0 * wy0, w10 = wx1 * wy0, w01 = wx0 * wy1, w11 = wx1 * wy1;
    int o00 = yc0 * WIMG + xc0, o10 = yc0 * WIMG + xc1;
    int o01 = yc1 * WIMG + xc0, o11 = yc1 * WIMG + xc1;

    const float* kb = key + ((size_t)img * EMBED + h * HD) * HW;
    const float* vb = val + ((size_t)img * EMBED + h * HD) * HW;

    __syncwarp();

    float a = 0.f;
    float* outvb = outv + (((size_t)n * NHD + h) * HD) * NP + p;
#pragma unroll 4
    for (int d = 0; d < HD; d++) {
        const float* kp = kb + d * HW;
        float ks = w00 * kp[o00] + w10 * kp[o10] + w01 * kp[o01] + w11 * kp[o11];
        a += qs[h][d] * ks;
        const float* vp = vb + d * HW;
        float vs = w00 * vp[o00] + w10 * vp[o10] + w01 * vp[o01] + w11 * vp[o11];
        vsm[h][d][p] = vs;
        outvb[d * NP] = vs;
    }
    a *= 0.17677669529663687f;
    size_t baseNP = ((size_t)n * NHD + h) * NP + p;
    outa[baseNP] = a;

    bool vx0 = (x0  >= 0) && (x0  < WIMG), vx1 = (x1i >= 0) && (x1i < WIMG);
    bool vy0 = (y0  >= 0) && (y0  < HIMG), vy1 = (y1i >= 0) && (y1i < HIMG);
    const float* mb = maskp + (size_t)img * HW;
    float mval = 0.f;
    if (vx0 && vy0) mval += w00 * mb[o00];
    if (vx1 && vy0) mval += w10 * mb[o10];
    if (vx0 && vy1) mval += w01 * mb[o01];
    if (vx1 && vy1) mval += w11 * mb[o11];
    outm[baseNP] = mval;

    const float* xb0 = x2d + (size_t)img * 2 * HW;
    const float* xb1 = xb0 + HW;
    float xs0 = w00 * xb0[o00] + w10 * xb0[o10] + w01 * xb0[o01] + w11 * xb0[o11];
    float xs1 = w00 * xb1[o00] + w10 * xb1[o10] + w01 * xb1[o01] + w11 * xb1[o11];
    size_t xbase = (((size_t)n * NHD + h) * 2) * NP + p;
    outx[xbase]      = xs0;
    outx[xbase + NP] = xs1;

    float mx = a;
#pragma unroll
    for (int o = 16; o; o >>= 1) mx = fmaxf(mx, __shfl_xor_sync(0xffffffffu, mx, o));
    float e = expf(a - mx);
    float ssum = e;
#pragma unroll
    for (int o = 16; o; o >>= 1) ssum += __shfl_xor_sync(0xffffffffu, ssum, o);
    float asv = e / ssum * mval;
    asms[h][p] = asv;
    __syncwarp();

    const int d = p;
    float o = 0.f;
#pragma unroll
    for (int pp = 0; pp < NP; pp++) o += asms[h][pp] * vsm[h][d][pp];
    attn[(size_t)n * EMBED + h * HD + d] = o;
}

// ============================================================================
extern "C" void kernel_launch(void* const* d_in, const int* in_sizes, int n_in,
                              void* d_out, int out_size)
{
    const float* query   = (const float*)d_in[0];
    const float* obj_emb = (const float*)d_in[1];
    const float* key_f   = (const float*)d_in[2];
    const float* value   = (const float*)d_in[3];
    const float* x2d     = (const float*)d_in[4];
    const float* maskp   = (const float*)d_in[5];
    const float* xy      = (const float*)d_in[6];
    const float* strides = (const float*)d_in[7];
    const int*   imgind  = (const int*  )d_in[8];
    const float* w_off   = (const float*)d_in[9];
    const float* b_off   = (const float*)d_in[10];
    const float* w_out   = (const float*)d_in[11];
    const float* b_out   = (const float*)d_in[12];
    const float* ln1g    = (const float*)d_in[13];
    const float* ln1b    = (const float*)d_in[14];
    const float* w1      = (const float*)d_in[15];
    const float* b1      = (const float*)d_in[16];
    const float* w2      = (const float*)d_in[17];
    const float* b2      = (const float*)d_in[18];
    const float* ln2g    = (const float*)d_in[19];
    const float* ln2b    = (const float*)d_in[20];

    float* out  = (float*)d_out;
    float* outv = out  + (size_t)NOBJ * EMBED;
    float* outa = outv + (size_t)NOBJ * NHD * HD * NP;
    float* outm = outa + (size_t)NOBJ * NHD * NP;
    float* outx = outm + (size_t)NOBJ * NHD * NP;

    float *p_loc, *p_attn, *p_x1ln, *p_hid, *p_part;
    cudaGetSymbolAddress((void**)&p_loc,  g_loc);
    cudaGetSymbolAddress((void**)&p_attn, g_attn);
    cudaGetSymbolAddress((void**)&p_x1ln, g_x1ln);
    cudaGetSymbolAddress((void**)&p_hid,  g_hid);
    cudaGetSymbolAddress((void**)&p_part, g_part);

    // 1) offsets GEMM (M=2048,N=512,K=256), split-K=2 -> partials (256 blocks)
    fgemm<4><<<dim3(512 / 64, NOBJ / 128, 2), 256>>>(
        obj_emb, w_off, nullptr, p_part, NOBJ, 512, EMBED, EMBED / 2);

    // 2) combine partials + bias -> sample coords
    coords_k<<<NOBJ, 256>>>(p_part, b_off, xy, strides, p_loc);

    // 3) gather + attention + sample outputs
    sampler_k<<<NOBJ, 256>>>(query, key_f, value, x2d, maskp, imgind, p_loc,
                             outv, outa, outm, outx, p_attn);

    // 4) w_out GEMM (K=256), split-K=4 -> partials (256 blocks)
    fgemm<4><<<dim3(EMBED / 64, NOBJ / 128, 4), 256>>>(
        p_attn, w_out, nullptr, p_part, NOBJ, EMBED, EMBED, EMBED / 4);

    // 5) combine + bias + residual(obj_emb) + LN1 -> x1ln
    comb_ln_k<4><<<NOBJ, 256>>>(p_part, b_out, obj_emb, ln1g, ln1b, p_x1ln);

    // 6) FFN up + relu (M=2048,N=1024,K=256) (256 blocks)
    fgemm<2><<<dim3(FFN_D / 64, NOBJ / 128, 1), 256>>>(
        p_x1ln, w1, b1, p_hid, NOBJ, FFN_D, EMBED, EMBED);

    // 7) FFN down GEMM (K=1024), split-K=4 -> partials (256 blocks)
    fgemm<4><<<dim3(EMBED / 64, NOBJ / 128, 4), 256>>>(
        p_hid, w2, nullptr, p_part, NOBJ, EMBED, FFN_D, FFN_D / 4);

    // 8) combine + bias + residual(x1ln) + LN2 -> final out
    comb_ln_k<4><<<NOBJ, 256>>>(p_part, b2, p_x1ln, ln2g, ln2b, out);
}